// round 10
// baseline (speedup 1.0000x reference)
#include <cuda_runtime.h>
#include <cuda_fp16.h>
#include <math.h>

#define FULL 0xffffffffu
#define MAXNR 131072
#define NBINS 257

typedef unsigned int uint;
typedef unsigned short ushort;

// Scratch (device globals; no allocation allowed).
// g_hist is zero-initialized at module load and re-zeroed by scan_kernel
// after each use, so no zeroing launch is needed.
__device__ float g_emb[MAXNR * 32];
__device__ int   g_hist[NBINS];
__device__ int   g_binbase[NBINS];
__device__ int   g_perm[MAXNR];

// ---------------------------------------------------------------------------
// helpers
// ---------------------------------------------------------------------------
__device__ __forceinline__ float tanhapx(float x) {
    float r; asm("tanh.approx.f32 %0, %1;" : "=f"(r) : "f"(x)); return r;
}
// pack two f32 into f16x2 (lo arg -> low half, hi arg -> high half)
__device__ __forceinline__ uint packhf(float lo, float hi) {
    uint r; asm("cvt.rn.f16x2.f32 %0, %1, %2;" : "=r"(r) : "f"(hi), "f"(lo)); return r;
}
__device__ __forceinline__ void mma_f16(
    float& d0, float& d1, float& d2, float& d3,
    uint a0, uint a1, uint a2, uint a3, uint b0, uint b1)
{
    asm("mma.sync.aligned.m16n8k16.row.col.f32.f16.f16.f32 "
        "{%0,%1,%2,%3}, {%4,%5,%6,%7}, {%8,%9}, {%0,%1,%2,%3};"
        : "+f"(d0), "+f"(d1), "+f"(d2), "+f"(d3)
        : "r"(a0), "r"(a1), "r"(a2), "r"(a3), "r"(b0), "r"(b1));
}
__device__ __forceinline__ void ldsm4t(uint& d0, uint& d1, uint& d2, uint& d3, uint saddr) {
    asm volatile("ldmatrix.sync.aligned.m8n8.x4.trans.shared.b16 {%0,%1,%2,%3}, [%4];"
        : "=r"(d0), "=r"(d1), "=r"(d2), "=r"(d3) : "r"(saddr));
}

// ---------------------------------------------------------------------------
// Counting sort by length (descending)
// ---------------------------------------------------------------------------
__global__ void hist_kernel(const int* __restrict__ l, int NR) {
    __shared__ int sh[NBINS];
    for (int i = threadIdx.x; i < NBINS; i += blockDim.x) sh[i] = 0;
    __syncthreads();
    int i = blockIdx.x * blockDim.x + threadIdx.x;
    if (i < NR) atomicAdd(&sh[l[i]], 1);
    __syncthreads();
    for (int i2 = threadIdx.x; i2 < NBINS; i2 += blockDim.x)
        if (sh[i2]) atomicAdd(&g_hist[i2], sh[i2]);
}

__global__ void scan_kernel() {   // 1 block, 512 threads
    __shared__ int s[512];
    int tid = threadIdx.x;
    int hv = (tid < NBINS) ? g_hist[256 - tid] : 0;
    // self-clean: leave g_hist zeroed for the next replay of this graph
    if (tid < NBINS) g_hist[256 - tid] = 0;
    s[tid] = hv;
    __syncthreads();
    for (int off = 1; off < 512; off <<= 1) {
        int v = (tid >= off) ? s[tid - off] : 0;
        __syncthreads();
        s[tid] += v;
        __syncthreads();
    }
    if (tid < NBINS) g_binbase[256 - tid] = s[tid] - hv;
}

__global__ void scatter_kernel(const int* __restrict__ l, int NR) {
    __shared__ int scount[NBINS];
    __shared__ int sbase[NBINS];
    for (int i = threadIdx.x; i < NBINS; i += blockDim.x) scount[i] = 0;
    __syncthreads();
    int i = blockIdx.x * blockDim.x + threadIdx.x;
    int len = 0, local = 0;
    if (i < NR) {
        len = l[i];
        local = atomicAdd(&scount[len], 1);
    }
    __syncthreads();
    for (int b = threadIdx.x; b < NBINS; b += blockDim.x)
        sbase[b] = scount[b] ? atomicAdd(&g_binbase[b], scount[b]) : 0;
    __syncthreads();
    if (i < NR) g_perm[sbase[len] + local] = i;
}

// ---------------------------------------------------------------------------
// RNN via fp16 2-term split tensor cores (m16n8k16; Whi*H + Wlo*H).
// H stored as ONE fp16 plane in shared, [j][s] layout, pad 40; B via
// ldmatrix.trans; finished columns frozen by predicated STS.16.
// ---------------------------------------------------------------------------
#define NW 4   // warps per block
#define HP 40  // H plane row pad (shorts)

__global__ __launch_bounds__(32 * NW, 5) void rnn_kernel(
    const float* __restrict__ h,
    const int*   __restrict__ l,
    const float* __restrict__ W_ih,
    const float* __restrict__ W_hh,
    const float* __restrict__ b_ih,
    const float* __restrict__ b_hh,
    int NR, int T)
{
    __shared__ __align__(16) ushort Hp[NW][32][HP];    // fp16 hidden, [j][s]
    __shared__ __align__(16) float  sx[NW][32][34];    // staged inputs [t&31][s]

    int tid  = threadIdx.x;
    int w    = tid >> 5;
    int lane = tid & 31;
    int gid  = lane >> 2;
    int tig  = lane & 3;

    // A fragments from global: exact fp16 split W = Whi + Wlo (+2^-24 residue)
    uint awhi[2][2][4], awlo[2][2][4];
#pragma unroll
    for (int m = 0; m < 2; m++)
#pragma unroll
        for (int kt = 0; kt < 2; kt++) {
            int r0 = 16 * m + gid, r1 = r0 + 8;
            int c0 = 16 * kt + 2 * tig, c2 = c0 + 8;
            int rr[4] = {r0, r1, r0, r1};
            int cc[4] = {c0, c0, c2, c2};
#pragma unroll
            for (int q = 0; q < 4; q++) {
                float w0 = __ldg(W_hh + rr[q] * 32 + cc[q]);
                float w1 = __ldg(W_hh + rr[q] * 32 + cc[q] + 1);
                float h0 = __half2float(__float2half_rn(w0));
                float h1 = __half2float(__float2half_rn(w1));
                awhi[m][kt][q] = packhf(h0, h1);
                awlo[m][kt][q] = packhf(w0 - h0, w1 - h1);
            }
        }

    float wih4[4], b4[4];
#pragma unroll
    for (int q = 0; q < 4; q++) {
        int r = gid + 8 * q;
        wih4[q] = __ldg(W_ih + r);
        b4[q]   = __ldg(b_ih + r) + __ldg(b_hh + r);
    }

    int warpbase = (blockIdx.x * NW + w) * 32;
    int gi  = warpbase + lane;
    int seq = (gi < NR) ? g_perm[gi] : 0;
    int len = (gi < NR) ? l[seq] : 0;
    int maxlen = __reduce_max_sync(FULL, len);

    int lencol[4][2];
#pragma unroll
    for (int n = 0; n < 4; n++)
#pragma unroll
        for (int u = 0; u < 2; u++)
            lencol[n][u] = __shfl_sync(FULL, len, 8 * n + 2 * tig + u);

    // zero hidden plane (len==0 columns stay zero forever = correct output)
    {
        uint* p0 = (uint*)&Hp[w][0][0];
        for (int q = lane; q < 32 * HP / 2; q += 32) p0[q] = 0;
    }
    __syncwarp();

    // ldmatrix per-lane base address
    int m8 = lane >> 3, r8 = lane & 7;
    uint lanoff = (uint)(((8 * (m8 & 1) + r8) * HP + 8 * (m8 >> 1)) * 2);
    uint hbase = (uint)__cvta_generic_to_shared(&Hp[w][0][0]) + lanoff;

    ushort* HW = &Hp[w][0][0];

    for (int t = 0; t < maxlen; t++) {
        if ((t & 31) == 0) {
            for (int s2 = 0; s2 < 32; s2++) {
                int sl = __shfl_sync(FULL, len, s2);
                int sq = __shfl_sync(FULL, seq, s2);
                int tt = t + lane;
                float v = 0.0f;
                if (tt < sl) v = __ldg(h + (size_t)sq * T + (sl - 1 - tt));
                sx[w][lane][s2] = v;
            }
            __syncwarp();
        }
        int tc = t & 31;

        // init accumulators with wih*x + bias
        float d[2][4][4];
#pragma unroll
        for (int n = 0; n < 4; n++) {
            float2 xv = *(const float2*)&sx[w][tc][8 * n + 2 * tig];
#pragma unroll
            for (int m = 0; m < 2; m++) {
                d[m][n][0] = fmaf(wih4[2 * m],     xv.x, b4[2 * m]);
                d[m][n][1] = fmaf(wih4[2 * m],     xv.y, b4[2 * m]);
                d[m][n][2] = fmaf(wih4[2 * m + 1], xv.x, b4[2 * m + 1]);
                d[m][n][3] = fmaf(wih4[2 * m + 1], xv.y, b4[2 * m + 1]);
            }
        }

        // GEMM: per (kt, nt-pair): 1 ldmatrix.x4.trans, then 2-term MMAs
#pragma unroll
        for (int kt = 0; kt < 2; kt++) {
#pragma unroll
            for (int ntp = 0; ntp < 2; ntp++) {
                uint off = (uint)((16 * kt * HP + 16 * ntp) * 2);
                uint bh0, bh1, bh2, bh3;
                ldsm4t(bh0, bh1, bh2, bh3, hbase + off);
                int n0 = 2 * ntp, n1 = n0 + 1;
#pragma unroll
                for (int m = 0; m < 2; m++) {
                    mma_f16(d[m][n0][0], d[m][n0][1], d[m][n0][2], d[m][n0][3],
                            awhi[m][kt][0], awhi[m][kt][1], awhi[m][kt][2], awhi[m][kt][3],
                            bh0, bh1);
                    mma_f16(d[m][n0][0], d[m][n0][1], d[m][n0][2], d[m][n0][3],
                            awlo[m][kt][0], awlo[m][kt][1], awlo[m][kt][2], awlo[m][kt][3],
                            bh0, bh1);
                    mma_f16(d[m][n1][0], d[m][n1][1], d[m][n1][2], d[m][n1][3],
                            awhi[m][kt][0], awhi[m][kt][1], awhi[m][kt][2], awhi[m][kt][3],
                            bh2, bh3);
                    mma_f16(d[m][n1][0], d[m][n1][1], d[m][n1][2], d[m][n1][3],
                            awlo[m][kt][0], awlo[m][kt][1], awlo[m][kt][2], awlo[m][kt][3],
                            bh2, bh3);
                }
            }
        }

        // epilogue: tanh + predicated fp16 stores (freeze finished columns)
        bool p[4][2];
#pragma unroll
        for (int n = 0; n < 4; n++) {
            p[n][0] = t < lencol[n][0];
            p[n][1] = t < lencol[n][1];
        }
#pragma unroll
        for (int m = 0; m < 2; m++) {
            int r0 = 16 * m + gid, r1 = r0 + 8;
#pragma unroll
            for (int n = 0; n < 4; n++) {
                int c0 = 8 * n + 2 * tig;
                float nh0 = tanhapx(d[m][n][0]);
                float nh1 = tanhapx(d[m][n][1]);
                float nh2 = tanhapx(d[m][n][2]);
                float nh3 = tanhapx(d[m][n][3]);
                if (p[n][0]) *(__half*)&HW[r0 * HP + c0]     = __float2half_rn(nh0);
                if (p[n][1]) *(__half*)&HW[r0 * HP + c0 + 1] = __float2half_rn(nh1);
                if (p[n][0]) *(__half*)&HW[r1 * HP + c0]     = __float2half_rn(nh2);
                if (p[n][1]) *(__half*)&HW[r1 * HP + c0 + 1] = __float2half_rn(nh3);
            }
        }
        __syncwarp();
    }

    // final h is frozen in the plane; write out (original order)
    for (int s2 = 0; s2 < 32; s2++) {
        if (warpbase + s2 < NR) {
            int sq = __shfl_sync(FULL, seq, s2);
            float hv = __half2float(*(__half*)&HW[lane * HP + s2]);
            g_emb[(size_t)sq * 32 + lane] = hv;
        }
    }
}

// ---------------------------------------------------------------------------
// MLP head: persistent blocks, warp-per-sample, grid-strided. Weights staged
// once per block and reused across ~14 samples per warp.
// ---------------------------------------------------------------------------
__global__ __launch_bounds__(256) void mlp_kernel(
    const float* __restrict__ W1, const float* __restrict__ b1,
    const float* __restrict__ W2, const float* __restrict__ b2,
    const float* __restrict__ W3, const float* __restrict__ b3,
    float* __restrict__ out, int N, int R)
{
    __shared__ float W1s[128 * 32];
    __shared__ float W2s[32 * 32];
    __shared__ float W3s[32 * 8];
    __shared__ float b1s[32], b2s[32], b3s[8];

    int tid = threadIdx.x;
    int RH  = R * 32;
    for (int i = tid; i < RH * 32; i += blockDim.x) W1s[i] = W1[i];
    for (int i = tid; i < 32 * 32; i += blockDim.x) W2s[i] = W2[i];
    for (int i = tid; i < 32 * R;  i += blockDim.x) W3s[i] = W3[i];
    if (tid < 32) { b1s[tid] = b1[tid]; b2s[tid] = b2[tid]; }
    if (tid < R)  b3s[tid] = b3[tid];
    __syncthreads();

    int wid  = tid >> 5;
    int lane = tid & 31;
    int wstride = gridDim.x * 8;

    for (int samp = blockIdx.x * 8 + wid; samp < N; samp += wstride) {
        float f0 = g_emb[((size_t)samp * R + 0) * 32 + lane];
        float f1 = g_emb[((size_t)samp * R + 1) * 32 + lane];
        float f2 = g_emb[((size_t)samp * R + 2) * 32 + lane];
        float f3 = g_emb[((size_t)samp * R + 3) * 32 + lane];

        float z = b1s[lane];
#pragma unroll
        for (int m = 0; m < 32; m++) {
            float fm = __shfl_sync(FULL, f0, m);
            z = fmaf(fm, W1s[m * 32 + lane], z);
        }
#pragma unroll
        for (int m = 0; m < 32; m++) {
            float fm = __shfl_sync(FULL, f1, m);
            z = fmaf(fm, W1s[(32 + m) * 32 + lane], z);
        }
#pragma unroll
        for (int m = 0; m < 32; m++) {
            float fm = __shfl_sync(FULL, f2, m);
            z = fmaf(fm, W1s[(64 + m) * 32 + lane], z);
        }
#pragma unroll
        for (int m = 0; m < 32; m++) {
            float fm = __shfl_sync(FULL, f3, m);
            z = fmaf(fm, W1s[(96 + m) * 32 + lane], z);
        }
        z = fmaxf(z, 0.0f);

        float z2 = b2s[lane];
#pragma unroll
        for (int m = 0; m < 32; m++) {
            float zm = __shfl_sync(FULL, z, m);
            z2 = fmaf(zm, W2s[m * 32 + lane], z2);
        }
        z2 = fmaxf(z2, 0.0f);

        for (int c = 0; c < R; c++) {
            float v = z2 * W3s[lane * R + c];
#pragma unroll
            for (int off = 16; off; off >>= 1) v += __shfl_xor_sync(FULL, v, off);
            if (lane == 0) out[(size_t)samp * R + c] = v + b3s[c];
        }
    }
}

// ---------------------------------------------------------------------------
// Launcher. Inputs: h, l, W_ih, W_hh, b_ih, b_hh, W1, b1, W2, b2, W3, b3
// ---------------------------------------------------------------------------
extern "C" void kernel_launch(void* const* d_in, const int* in_sizes, int n_in,
                              void* d_out, int out_size)
{
    const float* h    = (const float*)d_in[0];
    const int*   l    = (const int*)  d_in[1];
    const float* W_ih = (const float*)d_in[2];
    const float* W_hh = (const float*)d_in[3];
    const float* b_ih = (const float*)d_in[4];
    const float* b_hh = (const float*)d_in[5];
    const float* W1   = (const float*)d_in[6];
    const float* b1   = (const float*)d_in[7];
    const float* W2   = (const float*)d_in[8];
    const float* b2   = (const float*)d_in[9];
    const float* W3   = (const float*)d_in[10];
    const float* b3   = (const float*)d_in[11];
    float* out = (float*)d_out;

    int NR = in_sizes[1];
    int T  = in_sizes[0] / NR;
    int R  = in_sizes[10] / 32;
    int N  = NR / R;

    hist_kernel<<<(NR + 255) / 256, 256>>>(l, NR);
    scan_kernel<<<1, 512>>>();
    scatter_kernel<<<(NR + 255) / 256, 256>>>(l, NR);

    int warps = (NR + 31) / 32;
    rnn_kernel<<<(warps + NW - 1) / NW, 32 * NW>>>(h, l, W_ih, W_hh, b_ih, b_hh, NR, T);

    mlp_kernel<<<296, 256>>>(W1, b1, W2, b2, W3, b3, out, N, R);
}

// round 11
// speedup vs baseline: 1.0395x; 1.0395x over previous
#include <cuda_runtime.h>
#include <cuda_fp16.h>
#include <math.h>

#define FULL 0xffffffffu
#define MAXNR 131072
#define NBINS 257

typedef unsigned int uint;
typedef unsigned short ushort;

// Scratch (device globals; no allocation allowed).
// g_hist is zero-initialized at module load and re-zeroed by scan_kernel
// after each use, so no zeroing launch is needed.
__device__ float g_emb[MAXNR * 32];
__device__ int   g_hist[NBINS];
__device__ int   g_binbase[NBINS];
__device__ int   g_perm[MAXNR];

// ---------------------------------------------------------------------------
// helpers
// ---------------------------------------------------------------------------
__device__ __forceinline__ float tanhapx(float x) {
    float r; asm("tanh.approx.f32 %0, %1;" : "=f"(r) : "f"(x)); return r;
}
// pack two f32 into f16x2 (lo arg -> low half, hi arg -> high half)
__device__ __forceinline__ uint packhf(float lo, float hi) {
    uint r; asm("cvt.rn.f16x2.f32 %0, %1, %2;" : "=r"(r) : "f"(hi), "f"(lo)); return r;
}
__device__ __forceinline__ void mma_f16(
    float& d0, float& d1, float& d2, float& d3,
    uint a0, uint a1, uint a2, uint a3, uint b0, uint b1)
{
    asm("mma.sync.aligned.m16n8k16.row.col.f32.f16.f16.f32 "
        "{%0,%1,%2,%3}, {%4,%5,%6,%7}, {%8,%9}, {%0,%1,%2,%3};"
        : "+f"(d0), "+f"(d1), "+f"(d2), "+f"(d3)
        : "r"(a0), "r"(a1), "r"(a2), "r"(a3), "r"(b0), "r"(b1));
}
__device__ __forceinline__ void ldsm4t(uint& d0, uint& d1, uint& d2, uint& d3, uint saddr) {
    asm volatile("ldmatrix.sync.aligned.m8n8.x4.trans.shared.b16 {%0,%1,%2,%3}, [%4];"
        : "=r"(d0), "=r"(d1), "=r"(d2), "=r"(d3) : "r"(saddr));
}

// ---------------------------------------------------------------------------
// Counting sort by length (descending)
// ---------------------------------------------------------------------------
__global__ void hist_kernel(const int* __restrict__ l, int NR) {
    __shared__ int sh[NBINS];
    for (int i = threadIdx.x; i < NBINS; i += blockDim.x) sh[i] = 0;
    __syncthreads();
    int i = blockIdx.x * blockDim.x + threadIdx.x;
    if (i < NR) atomicAdd(&sh[l[i]], 1);
    __syncthreads();
    for (int i2 = threadIdx.x; i2 < NBINS; i2 += blockDim.x)
        if (sh[i2]) atomicAdd(&g_hist[i2], sh[i2]);
}

__global__ void scan_kernel() {   // 1 block, 512 threads
    __shared__ int s[512];
    int tid = threadIdx.x;
    int hv = (tid < NBINS) ? g_hist[256 - tid] : 0;
    // self-clean: leave g_hist zeroed for the next replay of this graph
    if (tid < NBINS) g_hist[256 - tid] = 0;
    s[tid] = hv;
    __syncthreads();
    for (int off = 1; off < 512; off <<= 1) {
        int v = (tid >= off) ? s[tid - off] : 0;
        __syncthreads();
        s[tid] += v;
        __syncthreads();
    }
    if (tid < NBINS) g_binbase[256 - tid] = s[tid] - hv;
}

__global__ void scatter_kernel(const int* __restrict__ l, int NR) {
    __shared__ int scount[NBINS];
    __shared__ int sbase[NBINS];
    for (int i = threadIdx.x; i < NBINS; i += blockDim.x) scount[i] = 0;
    __syncthreads();
    int i = blockIdx.x * blockDim.x + threadIdx.x;
    int len = 0, local = 0;
    if (i < NR) {
        len = l[i];
        local = atomicAdd(&scount[len], 1);
    }
    __syncthreads();
    for (int b = threadIdx.x; b < NBINS; b += blockDim.x)
        sbase[b] = scount[b] ? atomicAdd(&g_binbase[b], scount[b]) : 0;
    __syncthreads();
    if (i < NR) g_perm[sbase[len] + local] = i;
}

// ---------------------------------------------------------------------------
// RNN via fp16 2-term split tensor cores (m16n8k16; Whi*H + Wlo*H).
// H stored as ONE fp16 plane in shared, [j][s] layout, pad 40; B via
// ldmatrix.trans. Fast path (all 32 sorted columns active): packed
// unconditional STS.32. Slow path (near ends): predicated STS.16 freeze.
// ---------------------------------------------------------------------------
#define NW 4   // warps per block
#define HP 40  // H plane row pad (shorts)

__global__ __launch_bounds__(32 * NW, 4) void rnn_kernel(
    const float* __restrict__ h,
    const int*   __restrict__ l,
    const float* __restrict__ W_ih,
    const float* __restrict__ W_hh,
    const float* __restrict__ b_ih,
    const float* __restrict__ b_hh,
    int NR, int T)
{
    __shared__ __align__(16) ushort Hp[NW][32][HP];    // fp16 hidden, [j][s]
    __shared__ __align__(16) float  sx[NW][32][34];    // staged inputs [t&31][s]

    int tid  = threadIdx.x;
    int w    = tid >> 5;
    int lane = tid & 31;
    int gid  = lane >> 2;
    int tig  = lane & 3;

    // A fragments from global: exact fp16 split W = Whi + Wlo (+2^-24 residue)
    uint awhi[2][2][4], awlo[2][2][4];
#pragma unroll
    for (int m = 0; m < 2; m++)
#pragma unroll
        for (int kt = 0; kt < 2; kt++) {
            int r0 = 16 * m + gid, r1 = r0 + 8;
            int c0 = 16 * kt + 2 * tig, c2 = c0 + 8;
            int rr[4] = {r0, r1, r0, r1};
            int cc[4] = {c0, c0, c2, c2};
#pragma unroll
            for (int q = 0; q < 4; q++) {
                float w0 = __ldg(W_hh + rr[q] * 32 + cc[q]);
                float w1 = __ldg(W_hh + rr[q] * 32 + cc[q] + 1);
                float h0 = __half2float(__float2half_rn(w0));
                float h1 = __half2float(__float2half_rn(w1));
                awhi[m][kt][q] = packhf(h0, h1);
                awlo[m][kt][q] = packhf(w0 - h0, w1 - h1);
            }
        }

    float wih4[4], b4[4];
#pragma unroll
    for (int q = 0; q < 4; q++) {
        int r = gid + 8 * q;
        wih4[q] = __ldg(W_ih + r);
        b4[q]   = __ldg(b_ih + r) + __ldg(b_hh + r);
    }

    int warpbase = (blockIdx.x * NW + w) * 32;
    int gi  = warpbase + lane;
    int seq = (gi < NR) ? g_perm[gi] : 0;
    int len = (gi < NR) ? l[seq] : 0;
    int maxlen = __reduce_max_sync(FULL, len);
    int lenmin = __reduce_min_sync(FULL, len);

    int lencol[4][2];
#pragma unroll
    for (int n = 0; n < 4; n++)
#pragma unroll
        for (int u = 0; u < 2; u++)
            lencol[n][u] = __shfl_sync(FULL, len, 8 * n + 2 * tig + u);

    // zero hidden plane (len==0 columns stay zero forever = correct output)
    {
        uint* p0 = (uint*)&Hp[w][0][0];
        for (int q = lane; q < 32 * HP / 2; q += 32) p0[q] = 0;
    }
    __syncwarp();

    // ldmatrix per-lane base address
    int m8 = lane >> 3, r8 = lane & 7;
    uint lanoff = (uint)(((8 * (m8 & 1) + r8) * HP + 8 * (m8 >> 1)) * 2);
    uint hbase = (uint)__cvta_generic_to_shared(&Hp[w][0][0]) + lanoff;

    ushort* HW = &Hp[w][0][0];

    for (int t = 0; t < maxlen; t++) {
        if ((t & 31) == 0) {
            for (int s2 = 0; s2 < 32; s2++) {
                int sl = __shfl_sync(FULL, len, s2);
                int sq = __shfl_sync(FULL, seq, s2);
                int tt = t + lane;
                float v = 0.0f;
                if (tt < sl) v = __ldg(h + (size_t)sq * T + (sl - 1 - tt));
                sx[w][lane][s2] = v;
            }
            __syncwarp();
        }
        int tc = t & 31;

        // init accumulators with wih*x + bias
        float d[2][4][4];
#pragma unroll
        for (int n = 0; n < 4; n++) {
            float2 xv = *(const float2*)&sx[w][tc][8 * n + 2 * tig];
#pragma unroll
            for (int m = 0; m < 2; m++) {
                d[m][n][0] = fmaf(wih4[2 * m],     xv.x, b4[2 * m]);
                d[m][n][1] = fmaf(wih4[2 * m],     xv.y, b4[2 * m]);
                d[m][n][2] = fmaf(wih4[2 * m + 1], xv.x, b4[2 * m + 1]);
                d[m][n][3] = fmaf(wih4[2 * m + 1], xv.y, b4[2 * m + 1]);
            }
        }

        // GEMM: per (kt, nt-pair): 1 ldmatrix.x4.trans, then 2-term MMAs
#pragma unroll
        for (int kt = 0; kt < 2; kt++) {
#pragma unroll
            for (int ntp = 0; ntp < 2; ntp++) {
                uint off = (uint)((16 * kt * HP + 16 * ntp) * 2);
                uint bh0, bh1, bh2, bh3;
                ldsm4t(bh0, bh1, bh2, bh3, hbase + off);
                int n0 = 2 * ntp, n1 = n0 + 1;
#pragma unroll
                for (int m = 0; m < 2; m++) {
                    mma_f16(d[m][n0][0], d[m][n0][1], d[m][n0][2], d[m][n0][3],
                            awhi[m][kt][0], awhi[m][kt][1], awhi[m][kt][2], awhi[m][kt][3],
                            bh0, bh1);
                    mma_f16(d[m][n0][0], d[m][n0][1], d[m][n0][2], d[m][n0][3],
                            awlo[m][kt][0], awlo[m][kt][1], awlo[m][kt][2], awlo[m][kt][3],
                            bh0, bh1);
                    mma_f16(d[m][n1][0], d[m][n1][1], d[m][n1][2], d[m][n1][3],
                            awhi[m][kt][0], awhi[m][kt][1], awhi[m][kt][2], awhi[m][kt][3],
                            bh2, bh3);
                    mma_f16(d[m][n1][0], d[m][n1][1], d[m][n1][2], d[m][n1][3],
                            awlo[m][kt][0], awlo[m][kt][1], awlo[m][kt][2], awlo[m][kt][3],
                            bh2, bh3);
                }
            }
        }

        // epilogue
        if (t < lenmin) {
            // fast path: every column active -> unconditional packed stores
#pragma unroll
            for (int m = 0; m < 2; m++) {
                int r0 = 16 * m + gid, r1 = r0 + 8;
#pragma unroll
                for (int n = 0; n < 4; n++) {
                    int c0 = 8 * n + 2 * tig;
                    float nh0 = tanhapx(d[m][n][0]);
                    float nh1 = tanhapx(d[m][n][1]);
                    float nh2 = tanhapx(d[m][n][2]);
                    float nh3 = tanhapx(d[m][n][3]);
                    *(uint*)&HW[r0 * HP + c0] = packhf(nh0, nh1);
                    *(uint*)&HW[r1 * HP + c0] = packhf(nh2, nh3);
                }
            }
        } else {
            // slow path: predicated fp16 stores (freeze finished columns)
            bool p[4][2];
#pragma unroll
            for (int n = 0; n < 4; n++) {
                p[n][0] = t < lencol[n][0];
                p[n][1] = t < lencol[n][1];
            }
#pragma unroll
            for (int m = 0; m < 2; m++) {
                int r0 = 16 * m + gid, r1 = r0 + 8;
#pragma unroll
                for (int n = 0; n < 4; n++) {
                    int c0 = 8 * n + 2 * tig;
                    float nh0 = tanhapx(d[m][n][0]);
                    float nh1 = tanhapx(d[m][n][1]);
                    float nh2 = tanhapx(d[m][n][2]);
                    float nh3 = tanhapx(d[m][n][3]);
                    if (p[n][0]) *(__half*)&HW[r0 * HP + c0]     = __float2half_rn(nh0);
                    if (p[n][1]) *(__half*)&HW[r0 * HP + c0 + 1] = __float2half_rn(nh1);
                    if (p[n][0]) *(__half*)&HW[r1 * HP + c0]     = __float2half_rn(nh2);
                    if (p[n][1]) *(__half*)&HW[r1 * HP + c0 + 1] = __float2half_rn(nh3);
                }
            }
        }
        __syncwarp();
    }

    // final h is frozen in the plane; write out (original order)
    for (int s2 = 0; s2 < 32; s2++) {
        if (warpbase + s2 < NR) {
            int sq = __shfl_sync(FULL, seq, s2);
            float hv = __half2float(*(__half*)&HW[lane * HP + s2]);
            g_emb[(size_t)sq * 32 + lane] = hv;
        }
    }
}

// ---------------------------------------------------------------------------
// MLP head: persistent blocks, warp-per-sample, grid-strided. Weights staged
// once per block and reused across ~14 samples per warp.
// ---------------------------------------------------------------------------
__global__ __launch_bounds__(256) void mlp_kernel(
    const float* __restrict__ W1, const float* __restrict__ b1,
    const float* __restrict__ W2, const float* __restrict__ b2,
    const float* __restrict__ W3, const float* __restrict__ b3,
    float* __restrict__ out, int N, int R)
{
    __shared__ float W1s[128 * 32];
    __shared__ float W2s[32 * 32];
    __shared__ float W3s[32 * 8];
    __shared__ float b1s[32], b2s[32], b3s[8];

    int tid = threadIdx.x;
    int RH  = R * 32;
    for (int i = tid; i < RH * 32; i += blockDim.x) W1s[i] = W1[i];
    for (int i = tid; i < 32 * 32; i += blockDim.x) W2s[i] = W2[i];
    for (int i = tid; i < 32 * R;  i += blockDim.x) W3s[i] = W3[i];
    if (tid < 32) { b1s[tid] = b1[tid]; b2s[tid] = b2[tid]; }
    if (tid < R)  b3s[tid] = b3[tid];
    __syncthreads();

    int wid  = tid >> 5;
    int lane = tid & 31;
    int wstride = gridDim.x * 8;

    for (int samp = blockIdx.x * 8 + wid; samp < N; samp += wstride) {
        float f0 = g_emb[((size_t)samp * R + 0) * 32 + lane];
        float f1 = g_emb[((size_t)samp * R + 1) * 32 + lane];
        float f2 = g_emb[((size_t)samp * R + 2) * 32 + lane];
        float f3 = g_emb[((size_t)samp * R + 3) * 32 + lane];

        float z = b1s[lane];
#pragma unroll
        for (int m = 0; m < 32; m++) {
            float fm = __shfl_sync(FULL, f0, m);
            z = fmaf(fm, W1s[m * 32 + lane], z);
        }
#pragma unroll
        for (int m = 0; m < 32; m++) {
            float fm = __shfl_sync(FULL, f1, m);
            z = fmaf(fm, W1s[(32 + m) * 32 + lane], z);
        }
#pragma unroll
        for (int m = 0; m < 32; m++) {
            float fm = __shfl_sync(FULL, f2, m);
            z = fmaf(fm, W1s[(64 + m) * 32 + lane], z);
        }
#pragma unroll
        for (int m = 0; m < 32; m++) {
            float fm = __shfl_sync(FULL, f3, m);
            z = fmaf(fm, W1s[(96 + m) * 32 + lane], z);
        }
        z = fmaxf(z, 0.0f);

        float z2 = b2s[lane];
#pragma unroll
        for (int m = 0; m < 32; m++) {
            float zm = __shfl_sync(FULL, z, m);
            z2 = fmaf(zm, W2s[m * 32 + lane], z2);
        }
        z2 = fmaxf(z2, 0.0f);

        for (int c = 0; c < R; c++) {
            float v = z2 * W3s[lane * R + c];
#pragma unroll
            for (int off = 16; off; off >>= 1) v += __shfl_xor_sync(FULL, v, off);
            if (lane == 0) out[(size_t)samp * R + c] = v + b3s[c];
        }
    }
}

// ---------------------------------------------------------------------------
// Launcher. Inputs: h, l, W_ih, W_hh, b_ih, b_hh, W1, b1, W2, b2, W3, b3
// ---------------------------------------------------------------------------
extern "C" void kernel_launch(void* const* d_in, const int* in_sizes, int n_in,
                              void* d_out, int out_size)
{
    const float* h    = (const float*)d_in[0];
    const int*   l    = (const int*)  d_in[1];
    const float* W_ih = (const float*)d_in[2];
    const float* W_hh = (const float*)d_in[3];
    const float* b_ih = (const float*)d_in[4];
    const float* b_hh = (const float*)d_in[5];
    const float* W1   = (const float*)d_in[6];
    const float* b1   = (const float*)d_in[7];
    const float* W2   = (const float*)d_in[8];
    const float* b2   = (const float*)d_in[9];
    const float* W3   = (const float*)d_in[10];
    const float* b3   = (const float*)d_in[11];
    float* out = (float*)d_out;

    int NR = in_sizes[1];
    int T  = in_sizes[0] / NR;
    int R  = in_sizes[10] / 32;
    int N  = NR / R;

    hist_kernel<<<(NR + 255) / 256, 256>>>(l, NR);
    scan_kernel<<<1, 512>>>();
    scatter_kernel<<<(NR + 255) / 256, 256>>>(l, NR);

    int warps = (NR + 31) / 32;
    rnn_kernel<<<(warps + NW - 1) / NW, 32 * NW>>>(h, l, W_ih, W_hh, b_ih, b_hh, NR, T);

    mlp_kernel<<<296, 256>>>(W1, b1, W2, b2, W3, b3, out, N, R);
}

// round 12
// speedup vs baseline: 1.0694x; 1.0288x over previous
#include <cuda_runtime.h>
#include <cuda_fp16.h>
#include <math.h>

#define FULL 0xffffffffu
#define MAXNR 131072
#define NBINS 257

typedef unsigned int uint;
typedef unsigned short ushort;

// Scratch (device globals; no allocation allowed).
// g_hist is zero-initialized at module load and re-zeroed by scan_kernel
// after each use, so no zeroing launch is needed.
__device__ float g_emb[MAXNR * 32];
__device__ int   g_hist[NBINS];
__device__ int   g_binbase[NBINS];
__device__ int   g_perm[MAXNR];

// ---------------------------------------------------------------------------
// helpers
// ---------------------------------------------------------------------------
__device__ __forceinline__ float tanhapx(float x) {
    float r; asm("tanh.approx.f32 %0, %1;" : "=f"(r) : "f"(x)); return r;
}
// pack two f32 into f16x2 (lo arg -> low half, hi arg -> high half)
__device__ __forceinline__ uint packhf(float lo, float hi) {
    uint r; asm("cvt.rn.f16x2.f32 %0, %1, %2;" : "=r"(r) : "f"(hi), "f"(lo)); return r;
}
__device__ __forceinline__ void mma_f16(
    float& d0, float& d1, float& d2, float& d3,
    uint a0, uint a1, uint a2, uint a3, uint b0, uint b1)
{
    asm("mma.sync.aligned.m16n8k16.row.col.f32.f16.f16.f32 "
        "{%0,%1,%2,%3}, {%4,%5,%6,%7}, {%8,%9}, {%0,%1,%2,%3};"
        : "+f"(d0), "+f"(d1), "+f"(d2), "+f"(d3)
        : "r"(a0), "r"(a1), "r"(a2), "r"(a3), "r"(b0), "r"(b1));
}
__device__ __forceinline__ void ldsm4t(uint& d0, uint& d1, uint& d2, uint& d3, uint saddr) {
    asm volatile("ldmatrix.sync.aligned.m8n8.x4.trans.shared.b16 {%0,%1,%2,%3}, [%4];"
        : "=r"(d0), "=r"(d1), "=r"(d2), "=r"(d3) : "r"(saddr));
}

// ---------------------------------------------------------------------------
// Counting sort by length (descending)
// ---------------------------------------------------------------------------
__global__ void hist_kernel(const int* __restrict__ l, int NR) {
    __shared__ int sh[NBINS];
    for (int i = threadIdx.x; i < NBINS; i += blockDim.x) sh[i] = 0;
    __syncthreads();
    int i = blockIdx.x * blockDim.x + threadIdx.x;
    if (i < NR) atomicAdd(&sh[l[i]], 1);
    __syncthreads();
    for (int i2 = threadIdx.x; i2 < NBINS; i2 += blockDim.x)
        if (sh[i2]) atomicAdd(&g_hist[i2], sh[i2]);
}

__global__ void scan_kernel() {   // 1 block, 512 threads
    __shared__ int s[512];
    int tid = threadIdx.x;
    int hv = (tid < NBINS) ? g_hist[256 - tid] : 0;
    // self-clean: leave g_hist zeroed for the next replay of this graph
    if (tid < NBINS) g_hist[256 - tid] = 0;
    s[tid] = hv;
    __syncthreads();
    for (int off = 1; off < 512; off <<= 1) {
        int v = (tid >= off) ? s[tid - off] : 0;
        __syncthreads();
        s[tid] += v;
        __syncthreads();
    }
    if (tid < NBINS) g_binbase[256 - tid] = s[tid] - hv;
}

__global__ void scatter_kernel(const int* __restrict__ l, int NR) {
    __shared__ int scount[NBINS];
    __shared__ int sbase[NBINS];
    for (int i = threadIdx.x; i < NBINS; i += blockDim.x) scount[i] = 0;
    __syncthreads();
    int i = blockIdx.x * blockDim.x + threadIdx.x;
    int len = 0, local = 0;
    if (i < NR) {
        len = l[i];
        local = atomicAdd(&scount[len], 1);
    }
    __syncthreads();
    for (int b = threadIdx.x; b < NBINS; b += blockDim.x)
        sbase[b] = scount[b] ? atomicAdd(&g_binbase[b], scount[b]) : 0;
    __syncthreads();
    if (i < NR) g_perm[sbase[len] + local] = i;
}

// ---------------------------------------------------------------------------
// RNN via fp16 2-term split tensor cores (m16n8k16; Whi*H + Wlo*H).
// H stored as ONE fp16 plane in shared, [j][s] layout, pad 40; B via
// ldmatrix.trans; finished columns frozen by predicated STS.16.
// (Exact R9 configuration: regs ~96, occupancy 4 blocks/SM.)
// ---------------------------------------------------------------------------
#define NW 4   // warps per block
#define HP 40  // H plane row pad (shorts)

__global__ __launch_bounds__(32 * NW, 4) void rnn_kernel(
    const float* __restrict__ h,
    const int*   __restrict__ l,
    const float* __restrict__ W_ih,
    const float* __restrict__ W_hh,
    const float* __restrict__ b_ih,
    const float* __restrict__ b_hh,
    int NR, int T)
{
    __shared__ __align__(16) ushort Hp[NW][32][HP];    // fp16 hidden, [j][s]
    __shared__ __align__(16) float  sx[NW][32][34];    // staged inputs [t&31][s]

    int tid  = threadIdx.x;
    int w    = tid >> 5;
    int lane = tid & 31;
    int gid  = lane >> 2;
    int tig  = lane & 3;

    // A fragments from global: exact fp16 split W = Whi + Wlo (+2^-24 residue)
    uint awhi[2][2][4], awlo[2][2][4];
#pragma unroll
    for (int m = 0; m < 2; m++)
#pragma unroll
        for (int kt = 0; kt < 2; kt++) {
            int r0 = 16 * m + gid, r1 = r0 + 8;
            int c0 = 16 * kt + 2 * tig, c2 = c0 + 8;
            int rr[4] = {r0, r1, r0, r1};
            int cc[4] = {c0, c0, c2, c2};
#pragma unroll
            for (int q = 0; q < 4; q++) {
                float w0 = __ldg(W_hh + rr[q] * 32 + cc[q]);
                float w1 = __ldg(W_hh + rr[q] * 32 + cc[q] + 1);
                float h0 = __half2float(__float2half_rn(w0));
                float h1 = __half2float(__float2half_rn(w1));
                awhi[m][kt][q] = packhf(h0, h1);
                awlo[m][kt][q] = packhf(w0 - h0, w1 - h1);
            }
        }

    float wih4[4], b4[4];
#pragma unroll
    for (int q = 0; q < 4; q++) {
        int r = gid + 8 * q;
        wih4[q] = __ldg(W_ih + r);
        b4[q]   = __ldg(b_ih + r) + __ldg(b_hh + r);
    }

    int warpbase = (blockIdx.x * NW + w) * 32;
    int gi  = warpbase + lane;
    int seq = (gi < NR) ? g_perm[gi] : 0;
    int len = (gi < NR) ? l[seq] : 0;
    int maxlen = __reduce_max_sync(FULL, len);

    int lencol[4][2];
#pragma unroll
    for (int n = 0; n < 4; n++)
#pragma unroll
        for (int u = 0; u < 2; u++)
            lencol[n][u] = __shfl_sync(FULL, len, 8 * n + 2 * tig + u);

    // zero hidden plane (len==0 columns stay zero forever = correct output)
    {
        uint* p0 = (uint*)&Hp[w][0][0];
        for (int q = lane; q < 32 * HP / 2; q += 32) p0[q] = 0;
    }
    __syncwarp();

    // ldmatrix per-lane base address
    int m8 = lane >> 3, r8 = lane & 7;
    uint lanoff = (uint)(((8 * (m8 & 1) + r8) * HP + 8 * (m8 >> 1)) * 2);
    uint hbase = (uint)__cvta_generic_to_shared(&Hp[w][0][0]) + lanoff;

    ushort* HW = &Hp[w][0][0];

    for (int t = 0; t < maxlen; t++) {
        if ((t & 31) == 0) {
            for (int s2 = 0; s2 < 32; s2++) {
                int sl = __shfl_sync(FULL, len, s2);
                int sq = __shfl_sync(FULL, seq, s2);
                int tt = t + lane;
                float v = 0.0f;
                if (tt < sl) v = __ldg(h + (size_t)sq * T + (sl - 1 - tt));
                sx[w][lane][s2] = v;
            }
            __syncwarp();
        }
        int tc = t & 31;

        // init accumulators with wih*x + bias
        float d[2][4][4];
#pragma unroll
        for (int n = 0; n < 4; n++) {
            float2 xv = *(const float2*)&sx[w][tc][8 * n + 2 * tig];
#pragma unroll
            for (int m = 0; m < 2; m++) {
                d[m][n][0] = fmaf(wih4[2 * m],     xv.x, b4[2 * m]);
                d[m][n][1] = fmaf(wih4[2 * m],     xv.y, b4[2 * m]);
                d[m][n][2] = fmaf(wih4[2 * m + 1], xv.x, b4[2 * m + 1]);
                d[m][n][3] = fmaf(wih4[2 * m + 1], xv.y, b4[2 * m + 1]);
            }
        }

        // GEMM: per (kt, nt-pair): 1 ldmatrix.x4.trans, then 2-term MMAs
#pragma unroll
        for (int kt = 0; kt < 2; kt++) {
#pragma unroll
            for (int ntp = 0; ntp < 2; ntp++) {
                uint off = (uint)((16 * kt * HP + 16 * ntp) * 2);
                uint bh0, bh1, bh2, bh3;
                ldsm4t(bh0, bh1, bh2, bh3, hbase + off);
                int n0 = 2 * ntp, n1 = n0 + 1;
#pragma unroll
                for (int m = 0; m < 2; m++) {
                    mma_f16(d[m][n0][0], d[m][n0][1], d[m][n0][2], d[m][n0][3],
                            awhi[m][kt][0], awhi[m][kt][1], awhi[m][kt][2], awhi[m][kt][3],
                            bh0, bh1);
                    mma_f16(d[m][n0][0], d[m][n0][1], d[m][n0][2], d[m][n0][3],
                            awlo[m][kt][0], awlo[m][kt][1], awlo[m][kt][2], awlo[m][kt][3],
                            bh0, bh1);
                    mma_f16(d[m][n1][0], d[m][n1][1], d[m][n1][2], d[m][n1][3],
                            awhi[m][kt][0], awhi[m][kt][1], awhi[m][kt][2], awhi[m][kt][3],
                            bh2, bh3);
                    mma_f16(d[m][n1][0], d[m][n1][1], d[m][n1][2], d[m][n1][3],
                            awlo[m][kt][0], awlo[m][kt][1], awlo[m][kt][2], awlo[m][kt][3],
                            bh2, bh3);
                }
            }
        }

        // epilogue: tanh + predicated fp16 stores (freeze finished columns)
        bool p[4][2];
#pragma unroll
        for (int n = 0; n < 4; n++) {
            p[n][0] = t < lencol[n][0];
            p[n][1] = t < lencol[n][1];
        }
#pragma unroll
        for (int m = 0; m < 2; m++) {
            int r0 = 16 * m + gid, r1 = r0 + 8;
#pragma unroll
            for (int n = 0; n < 4; n++) {
                int c0 = 8 * n + 2 * tig;
                float nh0 = tanhapx(d[m][n][0]);
                float nh1 = tanhapx(d[m][n][1]);
                float nh2 = tanhapx(d[m][n][2]);
                float nh3 = tanhapx(d[m][n][3]);
                if (p[n][0]) *(__half*)&HW[r0 * HP + c0]     = __float2half_rn(nh0);
                if (p[n][1]) *(__half*)&HW[r0 * HP + c0 + 1] = __float2half_rn(nh1);
                if (p[n][0]) *(__half*)&HW[r1 * HP + c0]     = __float2half_rn(nh2);
                if (p[n][1]) *(__half*)&HW[r1 * HP + c0 + 1] = __float2half_rn(nh3);
            }
        }
        __syncwarp();
    }

    // final h is frozen in the plane; write out (original order)
    for (int s2 = 0; s2 < 32; s2++) {
        if (warpbase + s2 < NR) {
            int sq = __shfl_sync(FULL, seq, s2);
            float hv = __half2float(*(__half*)&HW[lane * HP + s2]);
            g_emb[(size_t)sq * 32 + lane] = hv;
        }
    }
}

// ---------------------------------------------------------------------------
// MLP head: persistent blocks, warp-per-sample, grid-strided. Weights staged
// once per block and reused across ~14 samples per warp.
// ---------------------------------------------------------------------------
__global__ __launch_bounds__(256) void mlp_kernel(
    const float* __restrict__ W1, const float* __restrict__ b1,
    const float* __restrict__ W2, const float* __restrict__ b2,
    const float* __restrict__ W3, const float* __restrict__ b3,
    float* __restrict__ out, int N, int R)
{
    __shared__ float W1s[128 * 32];
    __shared__ float W2s[32 * 32];
    __shared__ float W3s[32 * 8];
    __shared__ float b1s[32], b2s[32], b3s[8];

    int tid = threadIdx.x;
    int RH  = R * 32;
    for (int i = tid; i < RH * 32; i += blockDim.x) W1s[i] = W1[i];
    for (int i = tid; i < 32 * 32; i += blockDim.x) W2s[i] = W2[i];
    for (int i = tid; i < 32 * R;  i += blockDim.x) W3s[i] = W3[i];
    if (tid < 32) { b1s[tid] = b1[tid]; b2s[tid] = b2[tid]; }
    if (tid < R)  b3s[tid] = b3[tid];
    __syncthreads();

    int wid  = tid >> 5;
    int lane = tid & 31;
    int wstride = gridDim.x * 8;

    for (int samp = blockIdx.x * 8 + wid; samp < N; samp += wstride) {
        float f0 = g_emb[((size_t)samp * R + 0) * 32 + lane];
        float f1 = g_emb[((size_t)samp * R + 1) * 32 + lane];
        float f2 = g_emb[((size_t)samp * R + 2) * 32 + lane];
        float f3 = g_emb[((size_t)samp * R + 3) * 32 + lane];

        float z = b1s[lane];
#pragma unroll
        for (int m = 0; m < 32; m++) {
            float fm = __shfl_sync(FULL, f0, m);
            z = fmaf(fm, W1s[m * 32 + lane], z);
        }
#pragma unroll
        for (int m = 0; m < 32; m++) {
            float fm = __shfl_sync(FULL, f1, m);
            z = fmaf(fm, W1s[(32 + m) * 32 + lane], z);
        }
#pragma unroll
        for (int m = 0; m < 32; m++) {
            float fm = __shfl_sync(FULL, f2, m);
            z = fmaf(fm, W1s[(64 + m) * 32 + lane], z);
        }
#pragma unroll
        for (int m = 0; m < 32; m++) {
            float fm = __shfl_sync(FULL, f3, m);
            z = fmaf(fm, W1s[(96 + m) * 32 + lane], z);
        }
        z = fmaxf(z, 0.0f);

        float z2 = b2s[lane];
#pragma unroll
        for (int m = 0; m < 32; m++) {
            float zm = __shfl_sync(FULL, z, m);
            z2 = fmaf(zm, W2s[m * 32 + lane], z2);
        }
        z2 = fmaxf(z2, 0.0f);

        for (int c = 0; c < R; c++) {
            float v = z2 * W3s[lane * R + c];
#pragma unroll
            for (int off = 16; off; off >>= 1) v += __shfl_xor_sync(FULL, v, off);
            if (lane == 0) out[(size_t)samp * R + c] = v + b3s[c];
        }
    }
}

// ---------------------------------------------------------------------------
// Launcher. Inputs: h, l, W_ih, W_hh, b_ih, b_hh, W1, b1, W2, b2, W3, b3
// ---------------------------------------------------------------------------
extern "C" void kernel_launch(void* const* d_in, const int* in_sizes, int n_in,
                              void* d_out, int out_size)
{
    const float* h    = (const float*)d_in[0];
    const int*   l    = (const int*)  d_in[1];
    const float* W_ih = (const float*)d_in[2];
    const float* W_hh = (const float*)d_in[3];
    const float* b_ih = (const float*)d_in[4];
    const float* b_hh = (const float*)d_in[5];
    const float* W1   = (const float*)d_in[6];
    const float* b1   = (const float*)d_in[7];
    const float* W2   = (const float*)d_in[8];
    const float* b2   = (const float*)d_in[9];
    const float* W3   = (const float*)d_in[10];
    const float* b3   = (const float*)d_in[11];
    float* out = (float*)d_out;

    int NR = in_sizes[1];
    int T  = in_sizes[0] / NR;
    int R  = in_sizes[10] / 32;
    int N  = NR / R;

    hist_kernel<<<(NR + 255) / 256, 256>>>(l, NR);
    scan_kernel<<<1, 512>>>();
    scatter_kernel<<<(NR + 255) / 256, 256>>>(l, NR);

    int warps = (NR + 31) / 32;
    rnn_kernel<<<(warps + NW - 1) / NW, 32 * NW>>>(h, l, W_ih, W_hh, b_ih, b_hh, NR, T);

    mlp_kernel<<<296, 256>>>(W1, b1, W2, b2, W3, b3, out, N, R);
}

// round 13
// speedup vs baseline: 1.1686x; 1.0928x over previous
#include <cuda_runtime.h>
#include <cuda_fp16.h>
#include <math.h>

#define FULL 0xffffffffu
#define MAXNR 131072
#define NBINS 257

typedef unsigned int uint;
typedef unsigned short ushort;

// Scratch (device globals; no allocation allowed).
// g_hist is zero-initialized at module load and re-zeroed by scan_kernel
// after each use, so no zeroing launch is needed.
__device__ float g_emb[MAXNR * 32];
__device__ int   g_hist[NBINS];
__device__ int   g_binbase[NBINS];
__device__ int   g_perm[MAXNR];

// ---------------------------------------------------------------------------
// helpers
// ---------------------------------------------------------------------------
__device__ __forceinline__ float tanhapx(float x) {
    float r; asm("tanh.approx.f32 %0, %1;" : "=f"(r) : "f"(x)); return r;
}
// pack two f32 into f16x2 (lo arg -> low half, hi arg -> high half)
__device__ __forceinline__ uint packhf(float lo, float hi) {
    uint r; asm("cvt.rn.f16x2.f32 %0, %1, %2;" : "=r"(r) : "f"(hi), "f"(lo)); return r;
}
__device__ __forceinline__ void mma_f16(
    float& d0, float& d1, float& d2, float& d3,
    uint a0, uint a1, uint a2, uint a3, uint b0, uint b1)
{
    asm("mma.sync.aligned.m16n8k16.row.col.f32.f16.f16.f32 "
        "{%0,%1,%2,%3}, {%4,%5,%6,%7}, {%8,%9}, {%0,%1,%2,%3};"
        : "+f"(d0), "+f"(d1), "+f"(d2), "+f"(d3)
        : "r"(a0), "r"(a1), "r"(a2), "r"(a3), "r"(b0), "r"(b1));
}
__device__ __forceinline__ void ldsm4t(uint& d0, uint& d1, uint& d2, uint& d3, uint saddr) {
    asm volatile("ldmatrix.sync.aligned.m8n8.x4.trans.shared.b16 {%0,%1,%2,%3}, [%4];"
        : "=r"(d0), "=r"(d1), "=r"(d2), "=r"(d3) : "r"(saddr));
}

// ---------------------------------------------------------------------------
// Counting sort by length (descending)
// ---------------------------------------------------------------------------
__global__ void hist_kernel(const int* __restrict__ l, int NR) {
    __shared__ int sh[NBINS];
    for (int i = threadIdx.x; i < NBINS; i += blockDim.x) sh[i] = 0;
    __syncthreads();
    int i = blockIdx.x * blockDim.x + threadIdx.x;
    if (i < NR) atomicAdd(&sh[l[i]], 1);
    __syncthreads();
    for (int i2 = threadIdx.x; i2 < NBINS; i2 += blockDim.x)
        if (sh[i2]) atomicAdd(&g_hist[i2], sh[i2]);
}

__global__ void scan_kernel() {   // 1 block, 512 threads
    __shared__ int s[512];
    int tid = threadIdx.x;
    int hv = (tid < NBINS) ? g_hist[256 - tid] : 0;
    // self-clean: leave g_hist zeroed for the next replay of this graph
    if (tid < NBINS) g_hist[256 - tid] = 0;
    s[tid] = hv;
    __syncthreads();
    for (int off = 1; off < 512; off <<= 1) {
        int v = (tid >= off) ? s[tid - off] : 0;
        __syncthreads();
        s[tid] += v;
        __syncthreads();
    }
    if (tid < NBINS) g_binbase[256 - tid] = s[tid] - hv;
}

__global__ void scatter_kernel(const int* __restrict__ l, int NR) {
    __shared__ int scount[NBINS];
    __shared__ int sbase[NBINS];
    for (int i = threadIdx.x; i < NBINS; i += blockDim.x) scount[i] = 0;
    __syncthreads();
    int i = blockIdx.x * blockDim.x + threadIdx.x;
    int len = 0, local = 0;
    if (i < NR) {
        len = l[i];
        local = atomicAdd(&scount[len], 1);
    }
    __syncthreads();
    for (int b = threadIdx.x; b < NBINS; b += blockDim.x)
        sbase[b] = scount[b] ? atomicAdd(&g_binbase[b], scount[b]) : 0;
    __syncthreads();
    if (i < NR) g_perm[sbase[len] + local] = i;
}

// ---------------------------------------------------------------------------
// RNN via fp16 tensor cores (m16n8k16, single-term: fp16(W) * fp16(H)).
// H stored as ONE fp16 plane in shared, [j][s] layout, pad 40; B via
// ldmatrix.trans; finished columns frozen by predicated STS.16.
// 16 MMAs per warp-step.
// ---------------------------------------------------------------------------
#define NW 4   // warps per block
#define HP 40  // H plane row pad (shorts)

__global__ __launch_bounds__(32 * NW, 4) void rnn_kernel(
    const float* __restrict__ h,
    const int*   __restrict__ l,
    const float* __restrict__ W_ih,
    const float* __restrict__ W_hh,
    const float* __restrict__ b_ih,
    const float* __restrict__ b_hh,
    int NR, int T)
{
    __shared__ __align__(16) ushort Hp[NW][32][HP];    // fp16 hidden, [j][s]
    __shared__ __align__(16) float  sx[NW][32][34];    // staged inputs [t&31][s]

    int tid  = threadIdx.x;
    int w    = tid >> 5;
    int lane = tid & 31;
    int gid  = lane >> 2;
    int tig  = lane & 3;

    // A fragments from global, fp16-rounded: [m-tile][k-tile][reg]
    uint awf[2][2][4];
#pragma unroll
    for (int m = 0; m < 2; m++)
#pragma unroll
        for (int kt = 0; kt < 2; kt++) {
            int r0 = 16 * m + gid, r1 = r0 + 8;
            int c0 = 16 * kt + 2 * tig, c2 = c0 + 8;
            int rr[4] = {r0, r1, r0, r1};
            int cc[4] = {c0, c0, c2, c2};
#pragma unroll
            for (int q = 0; q < 4; q++) {
                float w0 = __ldg(W_hh + rr[q] * 32 + cc[q]);
                float w1 = __ldg(W_hh + rr[q] * 32 + cc[q] + 1);
                awf[m][kt][q] = packhf(w0, w1);
            }
        }

    float wih4[4], b4[4];
#pragma unroll
    for (int q = 0; q < 4; q++) {
        int r = gid + 8 * q;
        wih4[q] = __ldg(W_ih + r);
        b4[q]   = __ldg(b_ih + r) + __ldg(b_hh + r);
    }

    int warpbase = (blockIdx.x * NW + w) * 32;
    int gi  = warpbase + lane;
    int seq = (gi < NR) ? g_perm[gi] : 0;
    int len = (gi < NR) ? l[seq] : 0;
    int maxlen = __reduce_max_sync(FULL, len);

    int lencol[4][2];
#pragma unroll
    for (int n = 0; n < 4; n++)
#pragma unroll
        for (int u = 0; u < 2; u++)
            lencol[n][u] = __shfl_sync(FULL, len, 8 * n + 2 * tig + u);

    // zero hidden plane (len==0 columns stay zero forever = correct output)
    {
        uint* p0 = (uint*)&Hp[w][0][0];
        for (int q = lane; q < 32 * HP / 2; q += 32) p0[q] = 0;
    }
    __syncwarp();

    // ldmatrix per-lane base address
    int m8 = lane >> 3, r8 = lane & 7;
    uint lanoff = (uint)(((8 * (m8 & 1) + r8) * HP + 8 * (m8 >> 1)) * 2);
    uint hbase = (uint)__cvta_generic_to_shared(&Hp[w][0][0]) + lanoff;

    ushort* HW = &Hp[w][0][0];

    for (int t = 0; t < maxlen; t++) {
        if ((t & 31) == 0) {
            for (int s2 = 0; s2 < 32; s2++) {
                int sl = __shfl_sync(FULL, len, s2);
                int sq = __shfl_sync(FULL, seq, s2);
                int tt = t + lane;
                float v = 0.0f;
                if (tt < sl) v = __ldg(h + (size_t)sq * T + (sl - 1 - tt));
                sx[w][lane][s2] = v;
            }
            __syncwarp();
        }
        int tc = t & 31;

        // init accumulators with wih*x + bias
        float d[2][4][4];
#pragma unroll
        for (int n = 0; n < 4; n++) {
            float2 xv = *(const float2*)&sx[w][tc][8 * n + 2 * tig];
#pragma unroll
            for (int m = 0; m < 2; m++) {
                d[m][n][0] = fmaf(wih4[2 * m],     xv.x, b4[2 * m]);
                d[m][n][1] = fmaf(wih4[2 * m],     xv.y, b4[2 * m]);
                d[m][n][2] = fmaf(wih4[2 * m + 1], xv.x, b4[2 * m + 1]);
                d[m][n][3] = fmaf(wih4[2 * m + 1], xv.y, b4[2 * m + 1]);
            }
        }

        // GEMM: per (kt, nt-pair): 1 ldmatrix.x4.trans, then single-term MMAs
#pragma unroll
        for (int kt = 0; kt < 2; kt++) {
#pragma unroll
            for (int ntp = 0; ntp < 2; ntp++) {
                uint off = (uint)((16 * kt * HP + 16 * ntp) * 2);
                uint bh0, bh1, bh2, bh3;
                ldsm4t(bh0, bh1, bh2, bh3, hbase + off);
                int n0 = 2 * ntp, n1 = n0 + 1;
#pragma unroll
                for (int m = 0; m < 2; m++) {
                    mma_f16(d[m][n0][0], d[m][n0][1], d[m][n0][2], d[m][n0][3],
                            awf[m][kt][0], awf[m][kt][1], awf[m][kt][2], awf[m][kt][3],
                            bh0, bh1);
                    mma_f16(d[m][n1][0], d[m][n1][1], d[m][n1][2], d[m][n1][3],
                            awf[m][kt][0], awf[m][kt][1], awf[m][kt][2], awf[m][kt][3],
                            bh2, bh3);
                }
            }
        }

        // epilogue: tanh + predicated fp16 stores (freeze finished columns)
        bool p[4][2];
#pragma unroll
        for (int n = 0; n < 4; n++) {
            p[n][0] = t < lencol[n][0];
            p[n][1] = t < lencol[n][1];
        }
#pragma unroll
        for (int m = 0; m < 2; m++) {
            int r0 = 16 * m + gid, r1 = r0 + 8;
#pragma unroll
            for (int n = 0; n < 4; n++) {
                int c0 = 8 * n + 2 * tig;
                float nh0 = tanhapx(d[m][n][0]);
                float nh1 = tanhapx(d[m][n][1]);
                float nh2 = tanhapx(d[m][n][2]);
                float nh3 = tanhapx(d[m][n][3]);
                if (p[n][0]) *(__half*)&HW[r0 * HP + c0]     = __float2half_rn(nh0);
                if (p[n][1]) *(__half*)&HW[r0 * HP + c0 + 1] = __float2half_rn(nh1);
                if (p[n][0]) *(__half*)&HW[r1 * HP + c0]     = __float2half_rn(nh2);
                if (p[n][1]) *(__half*)&HW[r1 * HP + c0 + 1] = __float2half_rn(nh3);
            }
        }
        __syncwarp();
    }

    // final h is frozen in the plane; write out (original order)
    for (int s2 = 0; s2 < 32; s2++) {
        if (warpbase + s2 < NR) {
            int sq = __shfl_sync(FULL, seq, s2);
            float hv = __half2float(*(__half*)&HW[lane * HP + s2]);
            g_emb[(size_t)sq * 32 + lane] = hv;
        }
    }
}

// ---------------------------------------------------------------------------
// MLP head: persistent blocks, warp-per-sample, grid-strided. Weights staged
// once per block and reused across ~14 samples per warp.
// ---------------------------------------------------------------------------
__global__ __launch_bounds__(256) void mlp_kernel(
    const float* __restrict__ W1, const float* __restrict__ b1,
    const float* __restrict__ W2, const float* __restrict__ b2,
    const float* __restrict__ W3, const float* __restrict__ b3,
    float* __restrict__ out, int N, int R)
{
    __shared__ float W1s[128 * 32];
    __shared__ float W2s[32 * 32];
    __shared__ float W3s[32 * 8];
    __shared__ float b1s[32], b2s[32], b3s[8];

    int tid = threadIdx.x;
    int RH  = R * 32;
    for (int i = tid; i < RH * 32; i += blockDim.x) W1s[i] = W1[i];
    for (int i = tid; i < 32 * 32; i += blockDim.x) W2s[i] = W2[i];
    for (int i = tid; i < 32 * R;  i += blockDim.x) W3s[i] = W3[i];
    if (tid < 32) { b1s[tid] = b1[tid]; b2s[tid] = b2[tid]; }
    if (tid < R)  b3s[tid] = b3[tid];
    __syncthreads();

    int wid  = tid >> 5;
    int lane = tid & 31;
    int wstride = gridDim.x * 8;

    for (int samp = blockIdx.x * 8 + wid; samp < N; samp += wstride) {
        float f0 = g_emb[((size_t)samp * R + 0) * 32 + lane];
        float f1 = g_emb[((size_t)samp * R + 1) * 32 + lane];
        float f2 = g_emb[((size_t)samp * R + 2) * 32 + lane];
        float f3 = g_emb[((size_t)samp * R + 3) * 32 + lane];

        float z = b1s[lane];
#pragma unroll
        for (int m = 0; m < 32; m++) {
            float fm = __shfl_sync(FULL, f0, m);
            z = fmaf(fm, W1s[m * 32 + lane], z);
        }
#pragma unroll
        for (int m = 0; m < 32; m++) {
            float fm = __shfl_sync(FULL, f1, m);
            z = fmaf(fm, W1s[(32 + m) * 32 + lane], z);
        }
#pragma unroll
        for (int m = 0; m < 32; m++) {
            float fm = __shfl_sync(FULL, f2, m);
            z = fmaf(fm, W1s[(64 + m) * 32 + lane], z);
        }
#pragma unroll
        for (int m = 0; m < 32; m++) {
            float fm = __shfl_sync(FULL, f3, m);
            z = fmaf(fm, W1s[(96 + m) * 32 + lane], z);
        }
        z = fmaxf(z, 0.0f);

        float z2 = b2s[lane];
#pragma unroll
        for (int m = 0; m < 32; m++) {
            float zm = __shfl_sync(FULL, z, m);
            z2 = fmaf(zm, W2s[m * 32 + lane], z2);
        }
        z2 = fmaxf(z2, 0.0f);

        for (int c = 0; c < R; c++) {
            float v = z2 * W3s[lane * R + c];
#pragma unroll
            for (int off = 16; off; off >>= 1) v += __shfl_xor_sync(FULL, v, off);
            if (lane == 0) out[(size_t)samp * R + c] = v + b3s[c];
        }
    }
}

// ---------------------------------------------------------------------------
// Launcher. Inputs: h, l, W_ih, W_hh, b_ih, b_hh, W1, b1, W2, b2, W3, b3
// ---------------------------------------------------------------------------
extern "C" void kernel_launch(void* const* d_in, const int* in_sizes, int n_in,
                              void* d_out, int out_size)
{
    const float* h    = (const float*)d_in[0];
    const int*   l    = (const int*)  d_in[1];
    const float* W_ih = (const float*)d_in[2];
    const float* W_hh = (const float*)d_in[3];
    const float* b_ih = (const float*)d_in[4];
    const float* b_hh = (const float*)d_in[5];
    const float* W1   = (const float*)d_in[6];
    const float* b1   = (const float*)d_in[7];
    const float* W2   = (const float*)d_in[8];
    const float* b2   = (const float*)d_in[9];
    const float* W3   = (const float*)d_in[10];
    const float* b3   = (const float*)d_in[11];
    float* out = (float*)d_out;

    int NR = in_sizes[1];
    int T  = in_sizes[0] / NR;
    int R  = in_sizes[10] / 32;
    int N  = NR / R;

    hist_kernel<<<(NR + 255) / 256, 256>>>(l, NR);
    scan_kernel<<<1, 512>>>();
    scatter_kernel<<<(NR + 255) / 256, 256>>>(l, NR);

    int warps = (NR + 31) / 32;
    rnn_kernel<<<(warps + NW - 1) / NW, 32 * NW>>>(h, l, W_ih, W_hh, b_ih, b_hh, NR, T);

    mlp_kernel<<<296, 256>>>(W1, b1, W2, b2, W3, b3, out, N, R);
}